// round 10
// baseline (speedup 1.0000x reference)
#include <cuda_runtime.h>
#include <cuda_bf16.h>

#define MARGIN 0.5f
#define EPS 1e-6f
#define C_MAX 1024            // classes live in [0, 1000); padded
#define CAP 416               // max class rows cached in SMEM
#define THREADS_C 512
#define SMEM_BYTES (CAP * 512 + CAP * 4)   // rows (fp32) + sorted row ids

// Allocation-free scratch. __device__ globals are zero-initialized, so
// classes never written by bounds_kernel have cstart==cend==0 -> skipped.
__device__ double g_sum = 0.0;
__device__ unsigned int g_count = 0u;
__device__ int d_cstart[C_MAX];
__device__ int d_cend[C_MAX];

__device__ __forceinline__ float dsq(const float4 a, const float4 b)
{
    float d0 = a.x - b.x + EPS;
    float d1 = a.y - b.y + EPS;
    float d2 = a.z - b.z + EPS;
    float d3 = a.w - b.w + EPS;
    return fmaf(d0, d0, fmaf(d1, d1, fmaf(d2, d2, d3 * d3)));
}

// Triplets are contiguous per class (miner appends one chunk per class).
// Detect chunk boundaries via labels[a_idx[t]] transitions.
__global__ void bounds_kernel(const int* __restrict__ a_idx,
                              const int* __restrict__ labels, int T)
{
    const int t = blockIdx.x * blockDim.x + threadIdx.x;
    if (t >= T) return;
    const int c = labels[a_idx[t]];
    if (c < 0 || c >= C_MAX) return;
    if (t == 0 || labels[a_idx[t - 1]] != c) d_cstart[c] = t;
    if (t == T - 1) d_cend[c] = T;
    else if (labels[a_idx[t + 1]] != c) d_cend[c] = t + 1;
}

// One block per class. Phase 1: cache the class's rows (= its anchors, sorted
// ascending) in SMEM. Phase 2: half-warp per triplet; anchor+positive read
// from SMEM (positive located by binary search in the sorted id list,
// overlapped with the negative's GMEM gather).
__global__ void __launch_bounds__(THREADS_C, 1) class_kernel(
    const float* __restrict__ emb,
    const int* __restrict__ a_idx,
    const int* __restrict__ p_idx,
    const int* __restrict__ n_idx,
    int T,
    float* __restrict__ out)
{
    extern __shared__ float smem[];
    float* srows = smem;                         // CAP rows * 128 floats
    int* sids = (int*)(smem + CAP * 128);        // CAP sorted global row ids
    __shared__ float warp_vals[THREADS_C / 32];

    const int tid = threadIdx.x;
    const int wid = tid >> 5;
    const int lane = tid & 31;
    const int h = (tid >> 4) & 1;   // half within warp
    const int sl = tid & 15;        // sublane within half

    const int c = blockIdx.x;
    const int s = d_cstart[c];
    const int e = d_cend[c];
    float acc = 0.0f;

    if (s < e && e <= T) {
        const int m = e - s;
        if (m <= CAP) {
            // ---- Phase 1: stage class rows into SMEM (one warp per row) ----
            for (int r = wid; r < m; r += THREADS_C / 32) {
                const int g = __ldg(a_idx + s + r);
                if (lane == 0) sids[r] = g;
                const float4 v = __ldg(reinterpret_cast<const float4*>(emb + (size_t)g * 128) + lane);
                reinterpret_cast<float4*>(srows + (size_t)r * 128)[lane] = v;
            }
            __syncthreads();

            // ---- Phase 2: groups of 4 triplets per half-warp ----
            // Group base = k*128 + wid*8 + h*4 keeps the loop condition
            // warp-uniform (h-independent) so full-warp shuffles are safe.
            for (int kb = wid * 8; kb < m; kb += 128) {
                const int base = kb + h * 4;

                float4 nv0[4], nv1[4];
                int pslot[4];
                #pragma unroll
                for (int j = 0; j < 4; j++) {
                    const int lt = base + j;
                    const int tg = s + ((lt < m) ? lt : 0);
                    const int pj = __ldg(p_idx + tg);
                    const int nj = __ldg(n_idx + tg);
                    const float4* rn = reinterpret_cast<const float4*>(emb + (size_t)nj * 128) + sl;
                    nv0[j] = __ldg(rn);
                    nv1[j] = __ldg(rn + 16);
                    // Binary search pj in sorted sids (overlaps gather latency).
                    int lo = 0, hi = m - 1;
                    while (lo < hi) {
                        const int mid = (lo + hi) >> 1;
                        if (sids[mid] < pj) lo = mid + 1; else hi = mid;
                    }
                    pslot[j] = lo;
                }

                #pragma unroll
                for (int j = 0; j < 4; j++) {
                    const int lt = base + j;
                    const int aslot = (lt < m) ? lt : 0;
                    const float4* ra = reinterpret_cast<const float4*>(srows + (size_t)aslot * 128);
                    const float4* rp = reinterpret_cast<const float4*>(srows + (size_t)pslot[j] * 128);
                    const float4 av0 = ra[sl],      av1 = ra[sl + 16];
                    const float4 pv0 = rp[sl],      pv1 = rp[sl + 16];

                    float sp = dsq(av0, pv0) + dsq(av1, pv1);
                    float sn = dsq(av0, nv0[j]) + dsq(av1, nv1[j]);

                    #pragma unroll
                    for (int off = 8; off > 0; off >>= 1) {
                        sp += __shfl_down_sync(0xFFFFFFFFu, sp, off, 16);
                        sn += __shfl_down_sync(0xFFFFFFFFu, sn, off, 16);
                    }
                    if (sl == 0 && lt < m)
                        acc += fmaxf(sqrtf(sp) - sqrtf(sn) + MARGIN, 0.0f);
                }
            }
        } else {
            // ---- Fallback (class too large for SMEM): direct gathers ----
            for (int kb = wid * 2; kb < m; kb += 32) {
                const int lt = kb + h;
                const bool v = lt < m;
                const int tg = s + (v ? lt : 0);
                const int ia = __ldg(a_idx + tg);
                const int ip = __ldg(p_idx + tg);
                const int in = __ldg(n_idx + tg);
                const float4* ra = reinterpret_cast<const float4*>(emb + (size_t)ia * 128) + sl;
                const float4* rp = reinterpret_cast<const float4*>(emb + (size_t)ip * 128) + sl;
                const float4* rn = reinterpret_cast<const float4*>(emb + (size_t)in * 128) + sl;
                const float4 a0 = __ldg(ra), a1 = __ldg(ra + 16);
                const float4 p0 = __ldg(rp), p1 = __ldg(rp + 16);
                const float4 q0 = __ldg(rn), q1 = __ldg(rn + 16);

                float sp = dsq(a0, p0) + dsq(a1, p1);
                float sn = dsq(a0, q0) + dsq(a1, q1);
                #pragma unroll
                for (int off = 8; off > 0; off >>= 1) {
                    sp += __shfl_down_sync(0xFFFFFFFFu, sp, off, 16);
                    sn += __shfl_down_sync(0xFFFFFFFFu, sn, off, 16);
                }
                if (sl == 0 && v)
                    acc += fmaxf(sqrtf(sp) - sqrtf(sn) + MARGIN, 0.0f);
            }
        }
    }

    // ---- Block reduce + global accumulate + fused finalize ----
    #pragma unroll
    for (int off = 16; off > 0; off >>= 1)
        acc += __shfl_down_sync(0xFFFFFFFFu, acc, off);
    if (lane == 0) warp_vals[wid] = acc;
    __syncthreads();

    if (wid == 0) {
        float v = (lane < THREADS_C / 32) ? warp_vals[lane] : 0.0f;
        #pragma unroll
        for (int off = 8; off > 0; off >>= 1)
            v += __shfl_down_sync(0xFFFFFFFFu, v, off);

        if (lane == 0) {
            atomicAdd(&g_sum, (double)v);
            __threadfence();
            const unsigned int prev = atomicAdd(&g_count, 1u);
            if (prev == gridDim.x - 1) {
                const double total = atomicAdd(&g_sum, 0.0);
                out[0] = (float)(total / (double)T);
                g_sum = 0.0;
                __threadfence();
                atomicExch(&g_count, 0u);
            }
        }
    }
}

extern "C" void kernel_launch(void* const* d_in, const int* in_sizes, int n_in,
                              void* d_out, int out_size) {
    const float* emb   = (const float*)d_in[0];
    const int* labels  = (const int*)d_in[1];
    const int* a_idx   = (const int*)d_in[2];
    const int* p_idx   = (const int*)d_in[3];
    const int* n_idx   = (const int*)d_in[4];
    float* out         = (float*)d_out;

    const int T = in_sizes[2];

    // Opt in to large dynamic SMEM (idempotent; not a stream op).
    static bool attr_set = false;
    (void)attr_set;
    cudaFuncSetAttribute(class_kernel,
                         cudaFuncAttributeMaxDynamicSharedMemorySize,
                         SMEM_BYTES);

    bounds_kernel<<<(T + 255) / 256, 256>>>(a_idx, labels, T);
    class_kernel<<<C_MAX, THREADS_C, SMEM_BYTES>>>(emb, a_idx, p_idx, n_idx, T, out);
}

// round 11
// speedup vs baseline: 3.9438x; 3.9438x over previous
#include <cuda_runtime.h>
#include <cuda_bf16.h>

#define MARGIN 0.5f
#define EPS 1e-6f
#define WARPS_PER_BLOCK 8
#define THREADS (WARPS_PER_BLOCK * 32)
#define NSM 148
#define BLOCKS_PER_SM 4

// Allocation-free scratch; last finishing block resets for graph replays.
__device__ double g_sum = 0.0;
__device__ unsigned int g_count = 0u;

__device__ __forceinline__ float dsq(const float4 a, const float4 b)
{
    float d0 = a.x - b.x + EPS;
    float d1 = a.y - b.y + EPS;
    float d2 = a.z - b.z + EPS;
    float d3 = a.w - b.w + EPS;
    return fmaf(d0, d0, fmaf(d1, d1, fmaf(d2, d2, d3 * d3)));
}

// R6 kernel + SM-affinity remap: blocks with equal bid%148 co-reside on one
// SM (classic-launch placement, 4 resident blocks/SM). Remap virtual block id
// so co-resident blocks process adjacent triplet ranges -> their (same-class)
// anchor/positive rows stay hot in that SM's L1, bypassing the LTS cap.
__global__ void __launch_bounds__(THREADS, 4) triplet_kernel(
    const float* __restrict__ emb,
    const int* __restrict__ a_idx,
    const int* __restrict__ p_idx,
    const int* __restrict__ n_idx,
    int T,
    float* __restrict__ out)
{
    const int lane = threadIdx.x & 31;
    const int h = lane >> 4;      // which half-warp
    const int s = lane & 15;      // sublane within half
    const int warp_in_block = threadIdx.x >> 5;

    // Virtual block id: co-resident blocks get consecutive vb.
    const int vb = (blockIdx.x % NSM) * BLOCKS_PER_SM + (blockIdx.x / NSM);
    const int gwarp = vb * WARPS_PER_BLOCK + warp_in_block;
    const int nwarps = gridDim.x * WARPS_PER_BLOCK;

    float acc = 0.0f;

    for (int t0 = gwarp * 4; t0 < T; t0 += nwarps * 4) {
        const int tA = t0 + h;          // group A triplets: t0, t0+1
        const int tB = t0 + 2 + h;      // group B triplets: t0+2, t0+3
        const bool vA = (tA < T);
        const bool vB = (tB < T);
        const int cA = vA ? tA : 0;
        const int cB = vB ? tB : 0;

        const int iaA = a_idx[cA], ipA = p_idx[cA], inA = n_idx[cA];
        const int iaB = a_idx[cB], ipB = p_idx[cB], inB = n_idx[cB];

        const float4* raA = reinterpret_cast<const float4*>(emb + (size_t)iaA * 128) + s;
        const float4* rpA = reinterpret_cast<const float4*>(emb + (size_t)ipA * 128) + s;
        const float4* rnA = reinterpret_cast<const float4*>(emb + (size_t)inA * 128) + s;
        const float4* raB = reinterpret_cast<const float4*>(emb + (size_t)iaB * 128) + s;
        const float4* rpB = reinterpret_cast<const float4*>(emb + (size_t)ipB * 128) + s;
        const float4* rnB = reinterpret_cast<const float4*>(emb + (size_t)inB * 128) + s;

        // Issue all 12 loads up front (each covers two dense 256B blocks).
        const float4 aA0 = __ldg(raA),     aA1 = __ldg(raA + 16);
        const float4 pA0 = __ldg(rpA),     pA1 = __ldg(rpA + 16);
        const float4 nA0 = __ldg(rnA),     nA1 = __ldg(rnA + 16);
        const float4 aB0 = __ldg(raB),     aB1 = __ldg(raB + 16);
        const float4 pB0 = __ldg(rpB),     pB1 = __ldg(rpB + 16);
        const float4 nB0 = __ldg(rnB),     nB1 = __ldg(rnB + 16);

        float spA = dsq(aA0, pA0) + dsq(aA1, pA1);
        float snA = dsq(aA0, nA0) + dsq(aA1, nA1);
        float spB = dsq(aB0, pB0) + dsq(aB1, pB1);
        float snB = dsq(aB0, nB0) + dsq(aB1, nB1);

        // Reduce within each 16-lane half (both halves in parallel).
        #pragma unroll
        for (int off = 8; off > 0; off >>= 1) {
            spA += __shfl_down_sync(0xFFFFFFFFu, spA, off, 16);
            snA += __shfl_down_sync(0xFFFFFFFFu, snA, off, 16);
            spB += __shfl_down_sync(0xFFFFFFFFu, spB, off, 16);
            snB += __shfl_down_sync(0xFFFFFFFFu, snB, off, 16);
        }

        if (s == 0) {
            if (vA) acc += fmaxf(sqrtf(spA) - sqrtf(snA) + MARGIN, 0.0f);
            if (vB) acc += fmaxf(sqrtf(spB) - sqrtf(snB) + MARGIN, 0.0f);
        }
    }

    // Full warp reduce of acc (nonzero in lanes 0 and 16).
    #pragma unroll
    for (int off = 16; off > 0; off >>= 1)
        acc += __shfl_down_sync(0xFFFFFFFFu, acc, off);

    __shared__ float warp_vals[WARPS_PER_BLOCK];
    if (lane == 0) warp_vals[warp_in_block] = acc;
    __syncthreads();

    if (warp_in_block == 0) {
        float v = (lane < WARPS_PER_BLOCK) ? warp_vals[lane] : 0.0f;
        #pragma unroll
        for (int off = 4; off > 0; off >>= 1)
            v += __shfl_down_sync(0xFFFFFFFFu, v, off);

        if (lane == 0) {
            atomicAdd(&g_sum, (double)v);
            __threadfence();
            unsigned int prev = atomicAdd(&g_count, 1u);
            if (prev == gridDim.x - 1) {
                double total = atomicAdd(&g_sum, 0.0);
                out[0] = (float)(total / (double)T);
                g_sum = 0.0;
                __threadfence();
                atomicExch(&g_count, 0u);
            }
        }
    }
}

extern "C" void kernel_launch(void* const* d_in, const int* in_sizes, int n_in,
                              void* d_out, int out_size) {
    const float* emb   = (const float*)d_in[0];
    // d_in[1] = labels (unused; mining is precomputed in the reference inputs)
    const int* a_idx   = (const int*)d_in[2];
    const int* p_idx   = (const int*)d_in[3];
    const int* n_idx   = (const int*)d_in[4];
    float* out         = (float*)d_out;

    const int T = in_sizes[2];

    // Exactly 4 resident blocks per SM on 148 SMs (the remap assumes it).
    int blocks = NSM * BLOCKS_PER_SM;
    int max_blocks = (T + WARPS_PER_BLOCK * 4 - 1) / (WARPS_PER_BLOCK * 4);
    if (blocks > max_blocks) blocks = max_blocks;
    if (blocks < 1) blocks = 1;

    triplet_kernel<<<blocks, THREADS>>>(emb, a_idx, p_idx, n_idx, T, out);
}